// round 12
// baseline (speedup 1.0000x reference)
#include <cuda_runtime.h>
#include <cuda_bf16.h>

// Fixed problem shape: B=2, S=2048, D=2048, W=4.
#define SEQ   2048
#define DIM   2048
#define NT    512
#define TR    16                  // rows per CTA
#define EPSV  1e-6f
#define D4    (DIM / 4)           // float4s per row = 512
#define SLOT6(n) (((n) + 60) % 6) // 6-slot rolling window

// smem: part[TR][16 warps][64 partials] floats, then cs[TR] float4
#define PART_FLOATS (TR * 16 * 64)
#define SMEM_BYTES  ((PART_FLOATS + TR * 4) * 4)

typedef unsigned long long u64;

// ---- packed f32x2 helpers (sm_103a FFMA2 path) ----
static __device__ __forceinline__ u64 pk2(float lo, float hi) {
    u64 r; asm("mov.b64 %0, {%1, %2};" : "=l"(r) : "f"(lo), "f"(hi)); return r;
}
static __device__ __forceinline__ void up2(u64 v, float& lo, float& hi) {
    asm("mov.b64 {%0, %1}, %2;" : "=f"(lo), "=f"(hi) : "l"(v));
}
static __device__ __forceinline__ u64 mul2(u64 a, u64 b) {
    u64 r; asm("mul.rn.f32x2 %0, %1, %2;" : "=l"(r) : "l"(a), "l"(b)); return r;
}
static __device__ __forceinline__ u64 fma2(u64 a, u64 b, u64 c) {
    u64 r; asm("fma.rn.f32x2 %0, %1, %2, %3;" : "=l"(r) : "l"(a), "l"(b), "l"(c)); return r;
}

// Load W2[k][pair] = w[d][k]^2 for d = 4*tid..4*tid+3
static __device__ __forceinline__ void load_w2(const float4* __restrict__ w4,
                                               int tid, u64 W2p[4][2]) {
    float4 wq[4];
#pragma unroll
    for (int j = 0; j < 4; j++) wq[j] = __ldg(&w4[4 * tid + j]);
    const float wkj[4][4] = {
        {wq[0].x, wq[1].x, wq[2].x, wq[3].x},
        {wq[0].y, wq[1].y, wq[2].y, wq[3].y},
        {wq[0].z, wq[1].z, wq[2].z, wq[3].z},
        {wq[0].w, wq[1].w, wq[2].w, wq[3].w}};
#pragma unroll
    for (int k = 0; k < 4; k++) {
        W2p[k][0] = pk2(wkj[k][0] * wkj[k][0], wkj[k][1] * wkj[k][1]);
        W2p[k][1] = pk2(wkj[k][2] * wkj[k][2], wkj[k][3] * wkj[k][3]);
    }
}

__global__ __launch_bounds__(NT, 2)
void gated_fused(const float4* __restrict__ x4, const float4* __restrict__ w4,
                 const float*  __restrict__ alpha, const float4* __restrict__ rmsw4,
                 float4* __restrict__ out4)
{
    extern __shared__ float sm[];
    float*  part = sm;                       // [TR][16][64]
    float4* csm  = (float4*)(sm + PART_FLOATS); // [TR]

    const int tid  = threadIdx.x;
    const int lane = tid & 31;
    const int wid  = tid >> 5;
    const int s0   = blockIdx.x * TR;
    const int b    = blockIdx.y;

    const long base = ((long)b * SEQ) * D4 + tid;

    u64 W2p[4][2];
    load_w2(w4, tid, W2p);

    // ================= Phase 1: partials (no barriers) =================
    {
        u64 Xp[6][2];
#pragma unroll
        for (int j = 0; j <= 5; j++) {
            const int s  = s0 - j;
            const int sl = SLOT6(-j);
            if (s >= 0) {
                const float4 v = x4[base + (long)s * D4];
                Xp[sl][0] = pk2(v.x, v.y); Xp[sl][1] = pk2(v.z, v.w);
            } else {
                Xp[sl][0] = 0ull; Xp[sl][1] = 0ull;
            }
        }

#pragma unroll
        for (int t = 0; t < TR; t++) {
            if (t > 0) {
                const float4 v = x4[base + (long)(s0 + t) * D4];
                const int sl = SLOT6(t);
                Xp[sl][0] = pk2(v.x, v.y); Xp[sl][1] = pk2(v.z, v.w);
            }
            const int a0 = SLOT6(t),     a1 = SLOT6(t - 1), a2 = SLOT6(t - 2);
            const int a3 = SLOT6(t - 3), a4 = SLOT6(t - 4), a5 = SLOT6(t - 5);

            u64 vd0 = 0ull, vd1 = 0ull, vd2 = 0ull;
            u64 vv0 = 0ull, vv1 = 0ull, vv2 = 0ull, vv3 = 0ull;
#pragma unroll
            for (int p = 0; p < 2; p++) {
                const u64 x0 = Xp[a0][p], x1 = Xp[a1][p], x2 = Xp[a2][p];
                const u64 x3 = Xp[a3][p], x4v = Xp[a4][p], x5 = Xp[a5][p];
                vd0 = fma2(x0, x1, vd0);
                vd1 = fma2(x0, x2, vd1);
                vd2 = fma2(x0, x3, vd2);
                const u64 q0 = mul2(x0, x2);
                const u64 q1 = mul2(x1, x3);
                const u64 q2 = mul2(x2, x4v);
                const u64 q3 = mul2(x3, x5);
                vv0 = fma2(mul2(q0, q0), W2p[0][p], vv0);
                vv1 = fma2(mul2(q1, q1), W2p[1][p], vv1);
                vv2 = fma2(mul2(q2, q2), W2p[2][p], vv2);
                vv3 = fma2(mul2(q3, q3), W2p[3][p], vv3);
            }
            float v0, v1, v2, v3, v4, v5, v6;
            {
                float lo, hi;
                up2(vd0, lo, hi); v0 = lo + hi;
                up2(vd1, lo, hi); v1 = lo + hi;
                up2(vd2, lo, hi); v2 = lo + hi;
                up2(vv0, lo, hi); v3 = lo + hi;
                up2(vv1, lo, hi); v4 = lo + hi;
                up2(vv2, lo, hi); v5 = lo + hi;
                up2(vv3, lo, hi); v6 = lo + hi;
            }
            // 2-level butterfly: lane l ends holding partial (l&7) of every value
#pragma unroll
            for (int lvl = 16; lvl >= 8; lvl >>= 1) {
                v0 += __shfl_xor_sync(0xffffffffu, v0, lvl);
                v1 += __shfl_xor_sync(0xffffffffu, v1, lvl);
                v2 += __shfl_xor_sync(0xffffffffu, v2, lvl);
                v3 += __shfl_xor_sync(0xffffffffu, v3, lvl);
                v4 += __shfl_xor_sync(0xffffffffu, v4, lvl);
                v5 += __shfl_xor_sync(0xffffffffu, v5, lvl);
                v6 += __shfl_xor_sync(0xffffffffu, v6, lvl);
            }
            // store: value v = l>>3 at float index v*8+(l&7)  (== l)  [values 0..3]
            //        value 4+(l>>3) at 32+l                            [values 4..6]
            const int g = lane >> 3;
            const float st1 = (g == 0) ? v0 : (g == 1) ? v1 : (g == 2) ? v2 : v3;
            const float st2 = (g == 0) ? v4 : (g == 1) ? v5 : v6;
            float* dst = part + (t * 16 + wid) * 64;
            dst[lane] = st1;
            if (lane < 24) dst[32 + lane] = st2;
        }
    }
    __syncthreads();

    // ================= Phase 2: scales (warp r -> row r) =================
    if (wid < TR) {
        const float4* p = (const float4*)(part + wid * 1024);
        float4 acc = p[lane];
#pragma unroll
        for (int m = 1; m < 8; m++) {
            const float4 q = p[lane + 32 * m];
            acc.x += q.x; acc.y += q.y; acc.z += q.z; acc.w += q.w;
        }
        // lane l's acc covers value v=(l>>1)&7; combine lanes {l^1, l^16}
        float h = (acc.x + acc.y) + (acc.z + acc.w);
        h += __shfl_xor_sync(0xffffffffu, h, 1);
        h += __shfl_xor_sync(0xffffffffu, h, 16);
        // gather the 7 value-sums into every lane; lane 0 computes scales
        float sums[7];
#pragma unroll
        for (int v = 0; v < 7; v++)
            sums[v] = __shfl_sync(0xffffffffu, h, 2 * v);
        if (lane == 0) {
            const float invD = 1.0f / (float)DIM;
            float4 cs;
            cs.x = rsqrtf(sums[3] * invD + EPSV);
            cs.y = tanhf(sums[0] * __ldg(&alpha[0])) * rsqrtf(sums[4] * invD + EPSV);
            cs.z = tanhf(sums[1] * __ldg(&alpha[1])) * rsqrtf(sums[5] * invD + EPSV);
            cs.w = tanhf(sums[2] * __ldg(&alpha[2])) * rsqrtf(sums[6] * invD + EPSV);
            csm[wid] = cs;
        }
    }
    __syncthreads();

    // ================= Phase 3: streaming recombine (x re-read, warm) =================
    {
        const float4 rq = __ldg(&rmsw4[tid]);
        const u64 rp[2] = {pk2(rq.x, rq.y), pk2(rq.z, rq.w)};

        u64 Xp[6][2];
#pragma unroll
        for (int j = 0; j <= 5; j++) {
            const int s  = s0 - j;
            const int sl = SLOT6(-j);
            if (s >= 0) {
                const float4 v = x4[base + (long)s * D4];
                Xp[sl][0] = pk2(v.x, v.y); Xp[sl][1] = pk2(v.z, v.w);
            } else {
                Xp[sl][0] = 0ull; Xp[sl][1] = 0ull;
            }
        }

#pragma unroll
        for (int t = 0; t < TR; t++) {
            if (t > 0) {
                const float4 v = x4[base + (long)(s0 + t) * D4];
                const int sl = SLOT6(t);
                Xp[sl][0] = pk2(v.x, v.y); Xp[sl][1] = pk2(v.z, v.w);
            }
            const float4 cs = csm[t];
            const u64 cp0 = pk2(cs.x, cs.x), cp1 = pk2(cs.y, cs.y);
            const u64 cp2 = pk2(cs.z, cs.z), cp3 = pk2(cs.w, cs.w);

            const int a0 = SLOT6(t),     a1 = SLOT6(t - 1), a2 = SLOT6(t - 2);
            const int a3 = SLOT6(t - 3), a4 = SLOT6(t - 4), a5 = SLOT6(t - 5);

            float oo[4];
#pragma unroll
            for (int p = 0; p < 2; p++) {
                const u64 x0 = Xp[a0][p];
                const u64 q0 = mul2(x0, Xp[a2][p]);
                const u64 q1 = mul2(Xp[a1][p], Xp[a3][p]);
                const u64 q2 = mul2(Xp[a2][p], Xp[a4][p]);
                const u64 q3 = mul2(Xp[a3][p], Xp[a5][p]);
                u64 acc = mul2(cp0, mul2(q0, W2p[0][p]));
                acc = fma2(cp1, mul2(q1, W2p[1][p]), acc);
                acc = fma2(cp2, mul2(q2, W2p[2][p]), acc);
                acc = fma2(cp3, mul2(q3, W2p[3][p]), acc);
                const u64 o = fma2(rp[p], acc, x0);
                up2(o, oo[2 * p], oo[2 * p + 1]);
            }
            float4 ov; ov.x = oo[0]; ov.y = oo[1]; ov.z = oo[2]; ov.w = oo[3];
            out4[base + (long)(s0 + t) * D4] = ov;
        }
    }
}

extern "C" void kernel_launch(void* const* d_in, const int* in_sizes, int n_in,
                              void* d_out, int out_size)
{
    const float* x     = (const float*)d_in[0];
    const float* w     = (const float*)d_in[1];
    const float* alpha = (const float*)d_in[2];
    const float* rmsw  = (const float*)d_in[3];
    float* out = (float*)d_out;

    const long total = (long)in_sizes[0];
    const int  B     = (int)(total / ((long)SEQ * DIM));   // = 2

    static bool attr_done = false;
    if (!attr_done) {
        cudaFuncSetAttribute(gated_fused,
                             cudaFuncAttributeMaxDynamicSharedMemorySize, SMEM_BYTES);
        attr_done = true;
    }

    dim3 grid(SEQ / TR, B);
    gated_fused<<<grid, NT, SMEM_BYTES>>>((const float4*)x, (const float4*)w, alpha,
                                          (const float4*)rmsw, (float4*)out);
}

// round 14
// speedup vs baseline: 2.7477x; 2.7477x over previous
#include <cuda_runtime.h>
#include <cuda_bf16.h>

// Fixed problem shape: B=2, S=2048, D=2048, W=4.
#define SEQ   2048
#define DIM   2048
#define NT    512
#define TR1   16                  // rows per CTA, kernel 1
#define TR3   16                  // rows per CTA, kernel 3 (== #warps)
#define EPSV  1e-6f
#define D4    (DIM / 4)           // float4s per row = 512
#define SLOT6(n) (((n) + 60) % 6) // 6-slot rolling window

typedef unsigned long long u64;

// Scratch (device globals — no allocation). [b][s][val(7 pad 8)][warp]
__device__ float g_part[2][SEQ][8][16];

// ---- packed f32x2 helpers (sm_103a FFMA2 path) ----
static __device__ __forceinline__ u64 pk2(float lo, float hi) {
    u64 r; asm("mov.b64 %0, {%1, %2};" : "=l"(r) : "f"(lo), "f"(hi)); return r;
}
static __device__ __forceinline__ void up2(u64 v, float& lo, float& hi) {
    asm("mov.b64 {%0, %1}, %2;" : "=f"(lo), "=f"(hi) : "l"(v));
}
static __device__ __forceinline__ u64 mul2(u64 a, u64 b) {
    u64 r; asm("mul.rn.f32x2 %0, %1, %2;" : "=l"(r) : "l"(a), "l"(b)); return r;
}
static __device__ __forceinline__ u64 fma2(u64 a, u64 b, u64 c) {
    u64 r; asm("fma.rn.f32x2 %0, %1, %2, %3;" : "=l"(r) : "l"(a), "l"(b), "l"(c)); return r;
}

// Load W2[k][pair] = w[d][k]^2 for d = 4*tid..4*tid+3
static __device__ __forceinline__ void load_w2(const float4* __restrict__ w4,
                                               int tid, u64 W2p[4][2]) {
    float4 wq[4];
#pragma unroll
    for (int j = 0; j < 4; j++) wq[j] = __ldg(&w4[4 * tid + j]);
    const float wkj[4][4] = {
        {wq[0].x, wq[1].x, wq[2].x, wq[3].x},
        {wq[0].y, wq[1].y, wq[2].y, wq[3].y},
        {wq[0].z, wq[1].z, wq[2].z, wq[3].z},
        {wq[0].w, wq[1].w, wq[2].w, wq[3].w}};
#pragma unroll
    for (int k = 0; k < 4; k++) {
        W2p[k][0] = pk2(wkj[k][0] * wkj[k][0], wkj[k][1] * wkj[k][1]);
        W2p[k][1] = pk2(wkj[k][2] * wkj[k][2], wkj[k][3] * wkj[k][3]);
    }
}

// ============================ K1: per-warp partials ============================
__global__ __launch_bounds__(NT, 2)
void k_partials(const float4* __restrict__ x4, const float4* __restrict__ w4)
{
    const int tid  = threadIdx.x;
    const int lane = tid & 31;
    const int wid  = tid >> 5;
    const int s0   = blockIdx.x * TR1;
    const int b    = blockIdx.y;

    const long base = ((long)b * SEQ) * D4 + tid;

    u64 W2p[4][2];
    load_w2(w4, tid, W2p);

    // window: rows s0 .. s0-5
    u64 Xp[6][2];
#pragma unroll
    for (int j = 0; j <= 5; j++) {
        const int s  = s0 - j;
        const int sl = SLOT6(-j);
        if (s >= 0) {
            const float4 v = x4[base + (long)s * D4];
            Xp[sl][0] = pk2(v.x, v.y); Xp[sl][1] = pk2(v.z, v.w);
        } else {
            Xp[sl][0] = 0ull; Xp[sl][1] = 0ull;
        }
    }

    const int grp = lane >> 3;           // 0..3: which value this 8-lane block owns
    const bool store_lane = (lane & 7) == 0;

#pragma unroll
    for (int t = 0; t < TR1; t++) {
        if (t > 0) {
            const float4 v = x4[base + (long)(s0 + t) * D4];
            const int sl = SLOT6(t);
            Xp[sl][0] = pk2(v.x, v.y); Xp[sl][1] = pk2(v.z, v.w);
        }
        const int a0 = SLOT6(t),     a1 = SLOT6(t - 1), a2 = SLOT6(t - 2);
        const int a3 = SLOT6(t - 3), a4 = SLOT6(t - 4), a5 = SLOT6(t - 5);

        u64 vd0 = 0ull, vd1 = 0ull, vd2 = 0ull;
        u64 vv0 = 0ull, vv1 = 0ull, vv2 = 0ull, vv3 = 0ull;
#pragma unroll
        for (int p = 0; p < 2; p++) {
            const u64 x0 = Xp[a0][p], x1 = Xp[a1][p], x2 = Xp[a2][p];
            const u64 x3 = Xp[a3][p], x4v = Xp[a4][p], x5 = Xp[a5][p];
            vd0 = fma2(x0, x1, vd0);
            vd1 = fma2(x0, x2, vd1);
            vd2 = fma2(x0, x3, vd2);
            const u64 q0 = mul2(x0, x2);
            const u64 q1 = mul2(x1, x3);
            const u64 q2 = mul2(x2, x4v);
            const u64 q3 = mul2(x3, x5);
            vv0 = fma2(mul2(q0, q0), W2p[0][p], vv0);
            vv1 = fma2(mul2(q1, q1), W2p[1][p], vv1);
            vv2 = fma2(mul2(q2, q2), W2p[2][p], vv2);
            vv3 = fma2(mul2(q3, q3), W2p[3][p], vv3);
        }
        float v0, v1, v2, v3, v4, v5, v6;
        {
            float lo, hi;
            up2(vd0, lo, hi); v0 = lo + hi;
            up2(vd1, lo, hi); v1 = lo + hi;
            up2(vd2, lo, hi); v2 = lo + hi;
            up2(vv0, lo, hi); v3 = lo + hi;
            up2(vv1, lo, hi); v4 = lo + hi;
            up2(vv2, lo, hi); v5 = lo + hi;
            up2(vv3, lo, hi); v6 = lo + hi;
        }
        // 2-level butterfly: lane l holds partial for group (l&7), every value
#pragma unroll
        for (int lvl = 16; lvl >= 8; lvl >>= 1) {
            v0 += __shfl_xor_sync(0xffffffffu, v0, lvl);
            v1 += __shfl_xor_sync(0xffffffffu, v1, lvl);
            v2 += __shfl_xor_sync(0xffffffffu, v2, lvl);
            v3 += __shfl_xor_sync(0xffffffffu, v3, lvl);
            v4 += __shfl_xor_sync(0xffffffffu, v4, lvl);
            v5 += __shfl_xor_sync(0xffffffffu, v5, lvl);
            v6 += __shfl_xor_sync(0xffffffffu, v6, lvl);
        }
        // each 8-lane block finishes one value (a: 0..3, c: 4..6)
        float a = (grp == 0) ? v0 : (grp == 1) ? v1 : (grp == 2) ? v2 : v3;
        float c = (grp == 0) ? v4 : (grp == 1) ? v5 : v6;
#pragma unroll
        for (int lvl = 4; lvl >= 1; lvl >>= 1) {
            a += __shfl_xor_sync(0xffffffffu, a, lvl);
            c += __shfl_xor_sync(0xffffffffu, c, lvl);
        }
        if (store_lane) {
            g_part[b][s0 + t][grp][wid] = a;                    // values 0..3
            if (grp < 3) g_part[b][s0 + t][4 + grp][wid] = c;   // values 4..6
        }
    }
}

// ================= K3: scales (prologue) + streaming recombine =================
__global__ __launch_bounds__(NT, 2)
void k_combine(const float4* __restrict__ x4, const float4* __restrict__ w4,
               const float*  __restrict__ alpha, const float4* __restrict__ rmsw4,
               float4* __restrict__ out4)
{
    __shared__ float4 csm[TR3];

    const int tid  = threadIdx.x;
    const int lane = tid & 31;
    const int wid  = tid >> 5;
    const int s0   = blockIdx.x * TR3;
    const int b    = blockIdx.y;

    const long base = ((long)b * SEQ) * D4 + tid;

    // ---- prologue: warp r computes scales for row s0+r ----
    {
        float h = 0.f;
        if (lane < 28) {
            const float4 q = ((const float4*)&g_part[b][s0 + wid][0][0])[lane];
            h = ((q.x + q.y) + (q.z + q.w));
        }
        // lanes 4v..4v+3 hold chunk-partials of value v; reduce within group of 4
        h += __shfl_xor_sync(0xffffffffu, h, 1);
        h += __shfl_xor_sync(0xffffffffu, h, 2);
        // gather value-sums to ALL lanes (shfl must be warp-uniform!)
        float sums[7];
#pragma unroll
        for (int v = 0; v < 7; v++)
            sums[v] = __shfl_sync(0xffffffffu, h, 4 * v);
        if (lane == 0) {
            const float invD = 1.0f / (float)DIM;
            float4 cs;
            cs.x = rsqrtf(sums[3] * invD + EPSV);
            cs.y = tanhf(sums[0] * __ldg(&alpha[0])) * rsqrtf(sums[4] * invD + EPSV);
            cs.z = tanhf(sums[1] * __ldg(&alpha[1])) * rsqrtf(sums[5] * invD + EPSV);
            cs.w = tanhf(sums[2] * __ldg(&alpha[2])) * rsqrtf(sums[6] * invD + EPSV);
            csm[wid] = cs;
        }
    }

    u64 W2p[4][2];
    load_w2(w4, tid, W2p);
    const float4 rq = __ldg(&rmsw4[tid]);
    const u64 rp[2] = {pk2(rq.x, rq.y), pk2(rq.z, rq.w)};

    u64 Xp[6][2];
#pragma unroll
    for (int j = 0; j <= 5; j++) {
        const int s  = s0 - j;
        const int sl = SLOT6(-j);
        if (s >= 0) {
            const float4 v = x4[base + (long)s * D4];
            Xp[sl][0] = pk2(v.x, v.y); Xp[sl][1] = pk2(v.z, v.w);
        } else {
            Xp[sl][0] = 0ull; Xp[sl][1] = 0ull;
        }
    }

    __syncthreads();   // csm ready

#pragma unroll
    for (int t = 0; t < TR3; t++) {
        if (t > 0) {
            const float4 v = x4[base + (long)(s0 + t) * D4];
            const int sl = SLOT6(t);
            Xp[sl][0] = pk2(v.x, v.y); Xp[sl][1] = pk2(v.z, v.w);
        }
        const float4 cs = csm[t];
        const u64 cp0 = pk2(cs.x, cs.x), cp1 = pk2(cs.y, cs.y);
        const u64 cp2 = pk2(cs.z, cs.z), cp3 = pk2(cs.w, cs.w);

        const int a0 = SLOT6(t),     a1 = SLOT6(t - 1), a2 = SLOT6(t - 2);
        const int a3 = SLOT6(t - 3), a4 = SLOT6(t - 4), a5 = SLOT6(t - 5);

        float oo[4];
#pragma unroll
        for (int p = 0; p < 2; p++) {
            const u64 x0 = Xp[a0][p];
            const u64 q0 = mul2(x0, Xp[a2][p]);
            const u64 q1 = mul2(Xp[a1][p], Xp[a3][p]);
            const u64 q2 = mul2(Xp[a2][p], Xp[a4][p]);
            const u64 q3 = mul2(Xp[a3][p], Xp[a5][p]);
            u64 acc = mul2(cp0, mul2(q0, W2p[0][p]));
            acc = fma2(cp1, mul2(q1, W2p[1][p]), acc);
            acc = fma2(cp2, mul2(q2, W2p[2][p]), acc);
            acc = fma2(cp3, mul2(q3, W2p[3][p]), acc);
            const u64 o = fma2(rp[p], acc, x0);
            up2(o, oo[2 * p], oo[2 * p + 1]);
        }
        float4 ov; ov.x = oo[0]; ov.y = oo[1]; ov.z = oo[2]; ov.w = oo[3];
        out4[base + (long)(s0 + t) * D4] = ov;
    }
}

extern "C" void kernel_launch(void* const* d_in, const int* in_sizes, int n_in,
                              void* d_out, int out_size)
{
    const float* x     = (const float*)d_in[0];
    const float* w     = (const float*)d_in[1];
    const float* alpha = (const float*)d_in[2];
    const float* rmsw  = (const float*)d_in[3];
    float* out = (float*)d_out;

    const long total = (long)in_sizes[0];
    const int  B     = (int)(total / ((long)SEQ * DIM));   // = 2

    dim3 g1(SEQ / TR1, B);
    k_partials<<<g1, NT>>>((const float4*)x, (const float4*)w);

    dim3 g3(SEQ / TR3, B);
    k_combine<<<g3, NT>>>((const float4*)x, (const float4*)w, alpha,
                          (const float4*)rmsw, (float4*)out);
}